// round 1
// baseline (speedup 1.0000x reference)
#include <cuda_runtime.h>
#include <math.h>

#define BB 2
#define SS 1024
#define EE 512
#define HH 64
#define DKK 8
#define FF 2048
#define BS (BB*SS)   // 2048

// ---- scratch (device globals: allocation-free) ----
__device__ float g_q[BB*HH*SS*DKK];   // [B][H][S][8]   4 MB
__device__ float g_attn[BS*EE];       // [B*S][E]       4 MB
__device__ float g_x1[BS*EE];         //                4 MB
__device__ float g_qf[BS*EE];         //                4 MB
__device__ float g_hdn[BS*FF];        // [B*S][F]      16 MB

// exp2 on FMA pipe only: t in [-4.1, 4.1]; rel err ~2e-6
__device__ __forceinline__ float exp2_fast(float t) {
    float tm = t + 12582912.0f;              // round-to-nearest via magic
    float f  = t - (tm - 12582912.0f);       // f in [-0.5, 0.5]
    float p  = 1.0f + f*(0.6931471806f + f*(0.2402265069f + f*(0.0555041087f
             + f*(0.0096181291f + f*0.0013333558f))));
    return __int_as_float(__float_as_int(p) + (__float_as_int(tm) << 23));
}

// =====================================================================
// K1: ring expvals. q[b,h,s,d] from x[b,s,h*8+d] + theta
// =====================================================================
__global__ void qkv_kernel(const float* __restrict__ x,
                           const float* __restrict__ theta) {
    int i = blockIdx.x * 256 + threadIdx.x;       // over B*S*H = 131072
    int h  = i & (HH-1);
    int bs = i >> 6;
    const float* xp = x + bs*EE + h*DKK;
    float4 xa = *(const float4*)xp;
    float4 xb = *(const float4*)(xp + 4);
    float c0 = cosf(xa.x + theta[0]);
    float c1 = cosf(xa.y + theta[1]);
    float c2 = cosf(xa.z + theta[2]);
    float c3 = cosf(xa.w + theta[3]);
    float c4 = cosf(xb.x + theta[4]);
    float c5 = cosf(xb.y + theta[5]);
    float c6 = cosf(xb.z + theta[6]);
    float c7 = cosf(xb.w + theta[7]);
    float o1 = c0*c1;
    float o2 = o1*c2;
    float o3 = o2*c3;
    float o4 = o3*c4;
    float o5 = o4*c5;
    float o6 = o5*c6;
    float o7 = o6*c7;
    float o0 = c1*c2*c3*c4*c5*c6*c7;   // prod over wires 1..7
    int b = bs >> 10, s = bs & (SS-1);
    float* qp = g_q + (((b*HH + h)*SS) + s)*DKK;
    *(float4*)qp       = make_float4(o0, o1, o2, o3);
    *(float4*)(qp + 4) = make_float4(o4, o5, o6, o7);
}

// =====================================================================
// K2: attention per (b,h). q==k==v. scores bounded => no-max softmax.
// grid = B*H*(S/256) = 512 blocks, 256 threads, 1 row/thread.
// =====================================================================
__global__ void __launch_bounds__(256) attn_kernel() {
    __shared__ float Ksm[SS*DKK];                 // 32 KB: full K for this (b,h)
    int bh    = blockIdx.x >> 2;
    int chunk = blockIdx.x & 3;
    const float* qsrc = g_q + bh*SS*DKK;
    for (int j = threadIdx.x; j < SS*DKK/4; j += 256)
        ((float4*)Ksm)[j] = ((const float4*)qsrc)[j];
    __syncthreads();

    int row = chunk*256 + threadIdx.x;
    float4 q0 = *(float4*)(Ksm + row*DKK);
    float4 q1 = *(float4*)(Ksm + row*DKK + 4);

    const float SC = 0.35355339059f * 1.44269504f;   // 1/sqrt(8) * log2(e)
    float sum = 0.0f;
    float4 a0 = make_float4(0.f,0.f,0.f,0.f);
    float4 a1 = make_float4(0.f,0.f,0.f,0.f);
    #pragma unroll 4
    for (int t = 0; t < SS; t++) {
        float4 k0 = *(float4*)(Ksm + t*DKK);
        float4 k1 = *(float4*)(Ksm + t*DKK + 4);
        float d = q0.x*k0.x + q0.y*k0.y + q0.z*k0.z + q0.w*k0.w
                + q1.x*k1.x + q1.y*k1.y + q1.z*k1.z + q1.w*k1.w;
        float w = exp2_fast(d * SC);
        sum += w;
        a0.x = fmaf(w, k0.x, a0.x); a0.y = fmaf(w, k0.y, a0.y);
        a0.z = fmaf(w, k0.z, a0.z); a0.w = fmaf(w, k0.w, a0.w);
        a1.x = fmaf(w, k1.x, a1.x); a1.y = fmaf(w, k1.y, a1.y);
        a1.z = fmaf(w, k1.z, a1.z); a1.w = fmaf(w, k1.w, a1.w);
    }
    float inv = 1.0f / sum;
    int b = bh >> 6, h = bh & (HH-1);
    float* o = g_attn + (b*SS + row)*EE + h*DKK;
    *(float4*)o     = make_float4(a0.x*inv, a0.y*inv, a0.z*inv, a0.w*inv);
    *(float4*)(o+4) = make_float4(a1.x*inv, a1.y*inv, a1.z*inv, a1.w*inv);
}

// =====================================================================
// K3: combine GEMM [2048,512]@[512,512] + bias + residual + LN1,
// then qf = cos(x1)*cos(theta_ffn). 8 rows/block, 256 blocks.
// =====================================================================
extern __shared__ float smem_dyn[];

__global__ void __launch_bounds__(256) combine_kernel(
    const float* __restrict__ x,  const float* __restrict__ wc,
    const float* __restrict__ bc, const float* __restrict__ ln1w,
    const float* __restrict__ ln1b, const float* __restrict__ thf) {
    float* sA    = smem_dyn;        // 8*512
    float* costh = sA + 8*EE;       // 512
    const int rowbase = blockIdx.x * 8;
    const float* asrc = g_attn + rowbase*EE;
    for (int j = threadIdx.x; j < 8*EE/4; j += 256)
        ((float4*)sA)[j] = ((const float4*)asrc)[j];
    for (int j = threadIdx.x; j < EE; j += 256)
        costh[j] = cosf(thf[j]);
    __syncthreads();

    const int col = threadIdx.x * 2;
    float2 acc[8];
    #pragma unroll
    for (int r = 0; r < 8; r++) { acc[r].x = 0.f; acc[r].y = 0.f; }

    for (int k0 = 0; k0 < EE; k0 += 4) {
        float2 wl0 = *(const float2*)(wc + (k0+0)*EE + col);
        float2 wl1 = *(const float2*)(wc + (k0+1)*EE + col);
        float2 wl2 = *(const float2*)(wc + (k0+2)*EE + col);
        float2 wl3 = *(const float2*)(wc + (k0+3)*EE + col);
        #pragma unroll
        for (int r = 0; r < 8; r++) {
            float4 a = *(const float4*)(sA + r*EE + k0);
            acc[r].x = fmaf(a.w, wl3.x, fmaf(a.z, wl2.x, fmaf(a.y, wl1.x, fmaf(a.x, wl0.x, acc[r].x))));
            acc[r].y = fmaf(a.w, wl3.y, fmaf(a.z, wl2.y, fmaf(a.y, wl1.y, fmaf(a.x, wl0.y, acc[r].y))));
        }
    }

    __shared__ float redS[8][8], redQ[8][8];
    const int wid = threadIdx.x >> 5, lid = threadIdx.x & 31;
    float bx = bc[col], by = bc[col+1];
    float2 v[8];
    #pragma unroll
    for (int r = 0; r < 8; r++) {
        float2 xv = *(const float2*)(x + (rowbase+r)*EE + col);
        v[r].x = acc[r].x + bx + xv.x;
        v[r].y = acc[r].y + by + xv.y;
        float s = v[r].x + v[r].y;
        float q = v[r].x*v[r].x + v[r].y*v[r].y;
        #pragma unroll
        for (int o = 16; o; o >>= 1) {
            s += __shfl_xor_sync(0xffffffffu, s, o);
            q += __shfl_xor_sync(0xffffffffu, q, o);
        }
        if (lid == 0) { redS[r][wid] = s; redQ[r][wid] = q; }
    }
    __syncthreads();
    float lw0 = ln1w[col], lw1 = ln1w[col+1];
    float lb0 = ln1b[col], lb1 = ln1b[col+1];
    float ct0 = costh[col], ct1 = costh[col+1];
    #pragma unroll
    for (int r = 0; r < 8; r++) {
        float s = 0.f, q = 0.f;
        #pragma unroll
        for (int w = 0; w < 8; w++) { s += redS[r][w]; q += redQ[r][w]; }
        float mu   = s * (1.0f/EE);
        float var  = q * (1.0f/EE) - mu*mu;
        float rstd = rsqrtf(var + 1e-5f);
        float x1a = (v[r].x - mu)*rstd*lw0 + lb0;
        float x1b = (v[r].y - mu)*rstd*lw1 + lb1;
        *(float2*)(g_x1 + (rowbase+r)*EE + col) = make_float2(x1a, x1b);
        *(float2*)(g_qf + (rowbase+r)*EE + col) =
            make_float2(cosf(x1a)*ct0, cosf(x1b)*ct1);
    }
}

// =====================================================================
// K4: FFN1 [2048,512]@[512,2048] + bias + relu. 32 rows x 512-col chunk.
// grid = 64 rowblocks * 4 colchunks = 256.
// =====================================================================
__global__ void __launch_bounds__(256) ffn1_kernel(
    const float* __restrict__ w1, const float* __restrict__ b1) {
    float* sA = smem_dyn;                         // 32*512 = 64 KB
    const int rowbase = (blockIdx.x >> 2) * 32;
    const int colbase = (blockIdx.x & 3) * 512;
    const float* asrc = g_qf + rowbase*EE;
    for (int j = threadIdx.x; j < 32*EE/4; j += 256)
        ((float4*)sA)[j] = ((const float4*)asrc)[j];
    __syncthreads();

    const int col = colbase + threadIdx.x * 2;
    float2 acc[32];
    #pragma unroll
    for (int r = 0; r < 32; r++) { acc[r].x = 0.f; acc[r].y = 0.f; }

    for (int k0 = 0; k0 < EE; k0 += 4) {
        float2 wl0 = *(const float2*)(w1 + (k0+0)*FF + col);
        float2 wl1 = *(const float2*)(w1 + (k0+1)*FF + col);
        float2 wl2 = *(const float2*)(w1 + (k0+2)*FF + col);
        float2 wl3 = *(const float2*)(w1 + (k0+3)*FF + col);
        #pragma unroll
        for (int r = 0; r < 32; r++) {
            float4 a = *(const float4*)(sA + r*EE + k0);
            acc[r].x = fmaf(a.w, wl3.x, fmaf(a.z, wl2.x, fmaf(a.y, wl1.x, fmaf(a.x, wl0.x, acc[r].x))));
            acc[r].y = fmaf(a.w, wl3.y, fmaf(a.z, wl2.y, fmaf(a.y, wl1.y, fmaf(a.x, wl0.y, acc[r].y))));
        }
    }
    float bb0 = b1[col], bb1 = b1[col+1];
    #pragma unroll
    for (int r = 0; r < 32; r++) {
        float h0 = fmaxf(acc[r].x + bb0, 0.0f);
        float h1 = fmaxf(acc[r].y + bb1, 0.0f);
        *(float2*)(g_hdn + (rowbase+r)*FF + col) = make_float2(h0, h1);
    }
}

// =====================================================================
// K5: FFN2 [2048,2048]@[2048,512] + bias + residual + LN2 -> out.
// 16 rows/block (full E=512 cols), grid = 128. smem 128 KB.
// =====================================================================
__global__ void __launch_bounds__(256) ffn2_kernel(
    const float* __restrict__ w2, const float* __restrict__ b2,
    const float* __restrict__ ln2w, const float* __restrict__ ln2b,
    float* __restrict__ out) {
    float* sA = smem_dyn;                         // 16*2048 = 128 KB
    const int rowbase = blockIdx.x * 16;
    const float* asrc = g_hdn + rowbase*FF;
    for (int j = threadIdx.x; j < 16*FF/4; j += 256)
        ((float4*)sA)[j] = ((const float4*)asrc)[j];
    __syncthreads();

    const int col = threadIdx.x * 2;
    float2 acc[16];
    #pragma unroll
    for (int r = 0; r < 16; r++) { acc[r].x = 0.f; acc[r].y = 0.f; }

    for (int k0 = 0; k0 < FF; k0 += 4) {
        float2 wl0 = *(const float2*)(w2 + (k0+0)*EE + col);
        float2 wl1 = *(const float2*)(w2 + (k0+1)*EE + col);
        float2 wl2 = *(const float2*)(w2 + (k0+2)*EE + col);
        float2 wl3 = *(const float2*)(w2 + (k0+3)*EE + col);
        #pragma unroll
        for (int r = 0; r < 16; r++) {
            float4 a = *(const float4*)(sA + r*FF + k0);
            acc[r].x = fmaf(a.w, wl3.x, fmaf(a.z, wl2.x, fmaf(a.y, wl1.x, fmaf(a.x, wl0.x, acc[r].x))));
            acc[r].y = fmaf(a.w, wl3.y, fmaf(a.z, wl2.y, fmaf(a.y, wl1.y, fmaf(a.x, wl0.y, acc[r].y))));
        }
    }

    __shared__ float redS[16][8], redQ[16][8];
    const int wid = threadIdx.x >> 5, lid = threadIdx.x & 31;
    float bb0 = b2[col], bb1 = b2[col+1];
    float2 v[16];
    #pragma unroll
    for (int r = 0; r < 16; r++) {
        float2 xv = *(const float2*)(g_x1 + (rowbase+r)*EE + col);
        v[r].x = acc[r].x + bb0 + xv.x;
        v[r].y = acc[r].y + bb1 + xv.y;
        float s = v[r].x + v[r].y;
        float q = v[r].x*v[r].x + v[r].y*v[r].y;
        #pragma unroll
        for (int o = 16; o; o >>= 1) {
            s += __shfl_xor_sync(0xffffffffu, s, o);
            q += __shfl_xor_sync(0xffffffffu, q, o);
        }
        if (lid == 0) { redS[r][wid] = s; redQ[r][wid] = q; }
    }
    __syncthreads();
    float lw0 = ln2w[col], lw1 = ln2w[col+1];
    float lb0 = ln2b[col], lb1 = ln2b[col+1];
    #pragma unroll
    for (int r = 0; r < 16; r++) {
        float s = 0.f, q = 0.f;
        #pragma unroll
        for (int w = 0; w < 8; w++) { s += redS[r][w]; q += redQ[r][w]; }
        float mu   = s * (1.0f/EE);
        float var  = q * (1.0f/EE) - mu*mu;
        float rstd = rsqrtf(var + 1e-5f);
        float o0 = (v[r].x - mu)*rstd*lw0 + lb0;
        float o1 = (v[r].y - mu)*rstd*lw1 + lb1;
        *(float2*)(out + (rowbase+r)*EE + col) = make_float2(o0, o1);
    }
}

// =====================================================================
extern "C" void kernel_launch(void* const* d_in, const int* in_sizes, int n_in,
                              void* d_out, int out_size) {
    const float* x         = (const float*)d_in[0];
    const float* theta_at  = (const float*)d_in[1];
    const float* w_combine = (const float*)d_in[2];
    const float* b_combine = (const float*)d_in[3];
    const float* theta_ffn = (const float*)d_in[4];
    const float* w1        = (const float*)d_in[5];
    const float* b1        = (const float*)d_in[6];
    const float* w2        = (const float*)d_in[7];
    const float* b2        = (const float*)d_in[8];
    const float* ln1w      = (const float*)d_in[9];
    const float* ln1b      = (const float*)d_in[10];
    const float* ln2w      = (const float*)d_in[11];
    const float* ln2b      = (const float*)d_in[12];
    float* out = (float*)d_out;

    // opt-in smem (idempotent host calls; not stream ops, capture-safe)
    cudaFuncSetAttribute(ffn1_kernel, cudaFuncAttributeMaxDynamicSharedMemorySize, 32*EE*4);
    cudaFuncSetAttribute(ffn2_kernel, cudaFuncAttributeMaxDynamicSharedMemorySize, 16*FF*4);

    qkv_kernel<<<512, 256>>>(x, theta_at);
    attn_kernel<<<512, 256>>>();
    combine_kernel<<<256, 256, (8*EE + EE)*4>>>(x, w_combine, b_combine,
                                                ln1w, ln1b, theta_ffn);
    ffn1_kernel<<<256, 256, 32*EE*4>>>(w1, b1);
    ffn2_kernel<<<128, 256, 16*FF*4>>>(w2, b2, ln2w, ln2b, out);
}

// round 3
// speedup vs baseline: 1.6783x; 1.6783x over previous
#include <cuda_runtime.h>
#include <math.h>
#include <stdint.h>

#define BB 2
#define SS 1024
#define EE 512
#define HH 64
#define DKK 8
#define FF 2048
#define BS (BB*SS)   // 2048

// ---- scratch (device globals: allocation-free) ----
__device__ float g_q[BB*HH*SS*DKK];   // [B][H][S][8]
__device__ float g_attn[BS*EE];       // attention output (pre-combine)
__device__ float g_x1[BS*EE];         // post-LN1
__device__ float g_qf[BS*EE];         // cos(x1)*cos(theta)
__device__ float g_hdn[BS*FF];        // FFN hidden
__device__ float g_pre[BS*EE];        // pre-LN staging (reused for LN1 and LN2)

// exp2 on FMA pipe only: t in [-4.1, 4.1]; rel err ~2e-6
__device__ __forceinline__ float exp2_fast(float t) {
    float tm = t + 12582912.0f;
    float f  = t - (tm - 12582912.0f);
    float p  = 1.0f + f*(0.6931471806f + f*(0.2402265069f + f*(0.0555041087f
             + f*(0.0096181291f + f*0.0013333558f))));
    return __int_as_float(__float_as_int(p) + (__float_as_int(tm) << 23));
}

// tf32 cvt: destination must be a .b32 register (ptxas rejects f32 dst)
__device__ __forceinline__ float to_tf32(float x) {
    uint32_t r; asm("cvt.rna.tf32.f32 %0, %1;" : "=r"(r) : "f"(x));
    return __uint_as_float(r);
}
__device__ __forceinline__ float4 f4_tf32(float4 v) {
    v.x = to_tf32(v.x); v.y = to_tf32(v.y);
    v.z = to_tf32(v.z); v.w = to_tf32(v.w);
    return v;
}
__device__ __forceinline__ void mma_tf32(float* acc, float a0, float a1,
                                         float a2, float a3, float b0, float b1) {
    uint32_t A0 = __float_as_uint(a0), A1 = __float_as_uint(a1);
    uint32_t A2 = __float_as_uint(a2), A3 = __float_as_uint(a3);
    uint32_t B0 = __float_as_uint(b0), B1 = __float_as_uint(b1);
    asm volatile(
        "mma.sync.aligned.m16n8k8.row.col.f32.tf32.tf32.f32 "
        "{%0,%1,%2,%3},{%4,%5,%6,%7},{%8,%9},{%0,%1,%2,%3};"
        : "+f"(acc[0]), "+f"(acc[1]), "+f"(acc[2]), "+f"(acc[3])
        : "r"(A0), "r"(A1), "r"(A2), "r"(A3), "r"(B0), "r"(B1));
}

// =====================================================================
// K1: ring expvals
// =====================================================================
__global__ void qkv_kernel(const float* __restrict__ x,
                           const float* __restrict__ theta) {
    int i = blockIdx.x * 256 + threadIdx.x;       // over B*S*H = 131072
    int h  = i & (HH-1);
    int bs = i >> 6;
    const float* xp = x + bs*EE + h*DKK;
    float4 xa = *(const float4*)xp;
    float4 xb = *(const float4*)(xp + 4);
    float c0 = cosf(xa.x + theta[0]);
    float c1 = cosf(xa.y + theta[1]);
    float c2 = cosf(xa.z + theta[2]);
    float c3 = cosf(xa.w + theta[3]);
    float c4 = cosf(xb.x + theta[4]);
    float c5 = cosf(xb.y + theta[5]);
    float c6 = cosf(xb.z + theta[6]);
    float c7 = cosf(xb.w + theta[7]);
    float o1 = c0*c1;
    float o2 = o1*c2;
    float o3 = o2*c3;
    float o4 = o3*c4;
    float o5 = o4*c5;
    float o6 = o5*c6;
    float o7 = o6*c7;
    float o0 = c1*c2*c3*c4*c5*c6*c7;
    int b = bs >> 10, s = bs & (SS-1);
    float* qp = g_q + (((b*HH + h)*SS) + s)*DKK;
    *(float4*)qp       = make_float4(o0, o1, o2, o3);
    *(float4*)(qp + 4) = make_float4(o4, o5, o6, o7);
}

// =====================================================================
// K2: attention per (b,h). bounded scores -> no-max single-pass softmax.
// =====================================================================
__global__ void __launch_bounds__(256) attn_kernel() {
    __shared__ float Ksm[SS*DKK];                 // 32 KB
    int bh    = blockIdx.x >> 2;
    int chunk = blockIdx.x & 3;
    const float* qsrc = g_q + bh*SS*DKK;
    for (int j = threadIdx.x; j < SS*DKK/4; j += 256)
        ((float4*)Ksm)[j] = ((const float4*)qsrc)[j];
    __syncthreads();

    int row = chunk*256 + threadIdx.x;
    float4 q0 = *(float4*)(Ksm + row*DKK);
    float4 q1 = *(float4*)(Ksm + row*DKK + 4);

    const float SC = 0.35355339059f * 1.44269504f;   // 1/sqrt(8) * log2(e)
    float sum = 0.0f;
    float4 a0 = make_float4(0.f,0.f,0.f,0.f);
    float4 a1 = make_float4(0.f,0.f,0.f,0.f);
    #pragma unroll 4
    for (int t = 0; t < SS; t++) {
        float4 k0 = *(float4*)(Ksm + t*DKK);
        float4 k1 = *(float4*)(Ksm + t*DKK + 4);
        float d = q0.x*k0.x + q0.y*k0.y + q0.z*k0.z + q0.w*k0.w
                + q1.x*k1.x + q1.y*k1.y + q1.z*k1.z + q1.w*k1.w;
        float w = exp2_fast(d * SC);
        sum += w;
        a0.x = fmaf(w, k0.x, a0.x); a0.y = fmaf(w, k0.y, a0.y);
        a0.z = fmaf(w, k0.z, a0.z); a0.w = fmaf(w, k0.w, a0.w);
        a1.x = fmaf(w, k1.x, a1.x); a1.y = fmaf(w, k1.y, a1.y);
        a1.z = fmaf(w, k1.z, a1.z); a1.w = fmaf(w, k1.w, a1.w);
    }
    float inv = 1.0f / sum;
    int b = bh >> 6, h = bh & (HH-1);
    float* o = g_attn + (b*SS + row)*EE + h*DKK;
    *(float4*)o     = make_float4(a0.x*inv, a0.y*inv, a0.z*inv, a0.w*inv);
    *(float4*)(o+4) = make_float4(a1.x*inv, a1.y*inv, a1.z*inv, a1.w*inv);
}

// =====================================================================
// tf32 tensor-core GEMM: out[2048][N] = A[2048][KTOT] @ W[KTOT][N] (+bias,+res,relu)
// block tile 32x128, 8 warps (2M x 4N), warp tile 16x32 (4x m16n8k8 per k-step)
// =====================================================================
template<int KTOT, bool RELU>
__global__ void __launch_bounds__(256) mma_gemm_kernel(
    const float* __restrict__ A, const float* __restrict__ W,
    const float* __restrict__ bias, const float* __restrict__ res,
    float* __restrict__ out, int N)
{
    __shared__ float As[32][36];    // stride 36: frag LDS hits 32 distinct banks
    __shared__ float Bs[32][136];   // stride 136: ditto

    const int rowbase = blockIdx.y * 32;
    const int colbase = blockIdx.x * 128;
    const int tid  = threadIdx.x;
    const int warp = tid >> 5, lane = tid & 31;
    const int wm = warp >> 2;           // 0..1 (M)
    const int wn = warp & 3;            // 0..3 (N)
    const int g  = lane >> 2, tc = lane & 3;

    float acc[4][4];
    #pragma unroll
    for (int i = 0; i < 4; i++)
        #pragma unroll
        for (int j = 0; j < 4; j++) acc[i][j] = 0.f;

    // staging assignments
    const int arow = tid >> 3, ak = (tid & 7) * 4;   // A: 32x32 = 256 float4
    const float* Aptr = A + (rowbase + arow) * KTOT + ak;

    float4 aReg = *(const float4*)(Aptr);
    float4 bReg[4];
    #pragma unroll
    for (int i = 0; i < 4; i++) {
        int lin = tid + i*256;
        int br = lin >> 5, bc = (lin & 31) * 4;
        bReg[i] = *(const float4*)(W + br * N + colbase + bc);
    }

    const int NCHUNK = KTOT / 32;
    #pragma unroll 1
    for (int ch = 0; ch < NCHUNK; ch++) {
        __syncthreads();
        *(float4*)&As[arow][ak] = f4_tf32(aReg);
        #pragma unroll
        for (int i = 0; i < 4; i++) {
            int lin = tid + i*256;
            int br = lin >> 5, bc = (lin & 31) * 4;
            *(float4*)&Bs[br][bc] = f4_tf32(bReg[i]);
        }
        __syncthreads();

        if (ch + 1 < NCHUNK) {
            aReg = *(const float4*)(Aptr + (ch+1)*32);
            #pragma unroll
            for (int i = 0; i < 4; i++) {
                int lin = tid + i*256;
                int br = lin >> 5, bc = (lin & 31) * 4;
                bReg[i] = *(const float4*)(W + ((ch+1)*32 + br) * N + colbase + bc);
            }
        }

        #pragma unroll
        for (int ks = 0; ks < 4; ks++) {
            const int k0 = ks * 8;
            float a0 = As[wm*16 + g    ][k0 + tc];
            float a1 = As[wm*16 + g + 8][k0 + tc];
            float a2 = As[wm*16 + g    ][k0 + tc + 4];
            float a3 = As[wm*16 + g + 8][k0 + tc + 4];
            #pragma unroll
            for (int nt = 0; nt < 4; nt++) {
                int nb = wn*32 + nt*8 + g;
                float b0 = Bs[k0 + tc    ][nb];
                float b1 = Bs[k0 + tc + 4][nb];
                mma_tf32(acc[nt], a0, a1, a2, a3, b0, b1);
            }
        }
    }

    // epilogue: bias (+residual) (+relu)
    #pragma unroll
    for (int nt = 0; nt < 4; nt++) {
        int col = colbase + wn*32 + nt*8 + 2*tc;
        int r0 = rowbase + wm*16 + g;
        int r1 = r0 + 8;
        float bx = bias[col], by = bias[col+1];
        float2 v0 = make_float2(acc[nt][0] + bx, acc[nt][1] + by);
        float2 v1 = make_float2(acc[nt][2] + bx, acc[nt][3] + by);
        if (res != nullptr) {
            float2 s0 = *(const float2*)(res + r0*N + col);
            float2 s1 = *(const float2*)(res + r1*N + col);
            v0.x += s0.x; v0.y += s0.y;
            v1.x += s1.x; v1.y += s1.y;
        }
        if (RELU) {
            v0.x = fmaxf(v0.x, 0.f); v0.y = fmaxf(v0.y, 0.f);
            v1.x = fmaxf(v1.x, 0.f); v1.y = fmaxf(v1.y, 0.f);
        }
        *(float2*)(out + r0*N + col) = v0;
        *(float2*)(out + r1*N + col) = v1;
    }
}

// =====================================================================
// LN kernels: 1 row per block, 128 threads, float4 per thread
// =====================================================================
__global__ void __launch_bounds__(128) ln1_cos_kernel(
    const float* __restrict__ pre, const float* __restrict__ w,
    const float* __restrict__ b,   const float* __restrict__ thf)
{
    __shared__ float sS[4], sQ[4];
    const int row = blockIdx.x;
    const int t = threadIdx.x;
    float4 v = ((const float4*)(pre + row*EE))[t];
    float s = v.x + v.y + v.z + v.w;
    float q = v.x*v.x + v.y*v.y + v.z*v.z + v.w*v.w;
    #pragma unroll
    for (int o = 16; o; o >>= 1) {
        s += __shfl_xor_sync(0xffffffffu, s, o);
        q += __shfl_xor_sync(0xffffffffu, q, o);
    }
    if ((t & 31) == 0) { sS[t>>5] = s; sQ[t>>5] = q; }
    __syncthreads();
    s = sS[0] + sS[1] + sS[2] + sS[3];
    q = sQ[0] + sQ[1] + sQ[2] + sQ[3];
    float mu   = s * (1.0f/EE);
    float var  = q * (1.0f/EE) - mu*mu;
    float rstd = rsqrtf(var + 1e-5f);
    float4 lw = ((const float4*)w)[t];
    float4 lb = ((const float4*)b)[t];
    float4 th = ((const float4*)thf)[t];
    float4 x1;
    x1.x = (v.x - mu)*rstd*lw.x + lb.x;
    x1.y = (v.y - mu)*rstd*lw.y + lb.y;
    x1.z = (v.z - mu)*rstd*lw.z + lb.z;
    x1.w = (v.w - mu)*rstd*lw.w + lb.w;
    ((float4*)(g_x1 + row*EE))[t] = x1;
    float4 qf;
    qf.x = cosf(x1.x)*cosf(th.x);
    qf.y = cosf(x1.y)*cosf(th.y);
    qf.z = cosf(x1.z)*cosf(th.z);
    qf.w = cosf(x1.w)*cosf(th.w);
    ((float4*)(g_qf + row*EE))[t] = qf;
}

__global__ void __launch_bounds__(128) ln2_kernel(
    const float* __restrict__ pre, const float* __restrict__ w,
    const float* __restrict__ b,   float* __restrict__ out)
{
    __shared__ float sS[4], sQ[4];
    const int row = blockIdx.x;
    const int t = threadIdx.x;
    float4 v = ((const float4*)(pre + row*EE))[t];
    float s = v.x + v.y + v.z + v.w;
    float q = v.x*v.x + v.y*v.y + v.z*v.z + v.w*v.w;
    #pragma unroll
    for (int o = 16; o; o >>= 1) {
        s += __shfl_xor_sync(0xffffffffu, s, o);
        q += __shfl_xor_sync(0xffffffffu, q, o);
    }
    if ((t & 31) == 0) { sS[t>>5] = s; sQ[t>>5] = q; }
    __syncthreads();
    s = sS[0] + sS[1] + sS[2] + sS[3];
    q = sQ[0] + sQ[1] + sQ[2] + sQ[3];
    float mu   = s * (1.0f/EE);
    float var  = q * (1.0f/EE) - mu*mu;
    float rstd = rsqrtf(var + 1e-5f);
    float4 lw = ((const float4*)w)[t];
    float4 lb = ((const float4*)b)[t];
    float4 o4;
    o4.x = (v.x - mu)*rstd*lw.x + lb.x;
    o4.y = (v.y - mu)*rstd*lw.y + lb.y;
    o4.z = (v.z - mu)*rstd*lw.z + lb.z;
    o4.w = (v.w - mu)*rstd*lw.w + lb.w;
    ((float4*)(out + row*EE))[t] = o4;
}

// =====================================================================
extern "C" void kernel_launch(void* const* d_in, const int* in_sizes, int n_in,
                              void* d_out, int out_size) {
    const float* x         = (const float*)d_in[0];
    const float* theta_at  = (const float*)d_in[1];
    const float* w_combine = (const float*)d_in[2];
    const float* b_combine = (const float*)d_in[3];
    const float* theta_ffn = (const float*)d_in[4];
    const float* w1        = (const float*)d_in[5];
    const float* b1        = (const float*)d_in[6];
    const float* w2        = (const float*)d_in[7];
    const float* b2        = (const float*)d_in[8];
    const float* ln1w      = (const float*)d_in[9];
    const float* ln1b      = (const float*)d_in[10];
    const float* ln2w      = (const float*)d_in[11];
    const float* ln2b      = (const float*)d_in[12];
    float* out = (float*)d_out;

    float* d_q;    cudaGetSymbolAddress((void**)&d_q,    g_q);
    float* d_attn; cudaGetSymbolAddress((void**)&d_attn, g_attn);
    float* d_x1;   cudaGetSymbolAddress((void**)&d_x1,   g_x1);
    float* d_qf;   cudaGetSymbolAddress((void**)&d_qf,   g_qf);
    float* d_hdn;  cudaGetSymbolAddress((void**)&d_hdn,  g_hdn);
    float* d_pre;  cudaGetSymbolAddress((void**)&d_pre,  g_pre);

    qkv_kernel<<<512, 256>>>(x, theta_at);
    attn_kernel<<<512, 256>>>();

    // combine: g_attn[2048,512] @ wc[512,512] + bias + x  -> g_pre
    mma_gemm_kernel<512, false><<<dim3(4, 64), 256>>>(
        d_attn, w_combine, b_combine, x, d_pre, EE);
    ln1_cos_kernel<<<BS, 128>>>(d_pre, ln1w, ln1b, theta_ffn);

    // ffn1: g_qf[2048,512] @ w1[512,2048] + b1, relu -> g_hdn
    mma_gemm_kernel<512, true><<<dim3(16, 64), 256>>>(
        d_qf, w1, b1, nullptr, d_hdn, FF);

    // ffn2: g_hdn[2048,2048] @ w2[2048,512] + b2 + g_x1 -> g_pre
    mma_gemm_kernel<2048, false><<<dim3(4, 64), 256>>>(
        d_hdn, w2, b2, d_x1, d_pre, EE);
    ln2_kernel<<<BS, 128>>>(d_pre, ln2w, ln2b, out);
}

// round 4
// speedup vs baseline: 2.1167x; 1.2612x over previous
#include <cuda_runtime.h>
#include <math.h>
#include <stdint.h>

#define BB 2
#define SS 1024
#define EE 512
#define HH 64
#define DKK 8
#define FF 2048
#define BS (BB*SS)   // 2048

// ---- scratch (device globals: allocation-free) ----
__device__ float g_q[BB*HH*SS*DKK];   // [B][H][S][8]
__device__ float g_attn[BS*EE];       // attention output (pre-combine)
__device__ float g_x1[BS*EE];         // post-LN1
__device__ float g_qf[BS*EE];         // cos(x1)*cos(theta)
__device__ float g_hdn[BS*FF];        // FFN hidden
__device__ float g_pre[BS*EE];        // pre-LN staging

// deg-4 exp2 poly on FMA pipe, t in [-4.1, 4.1], rel err ~4e-5
__device__ __forceinline__ float exp2p(float t) {
    float tm = t + 12582912.0f;
    float f  = t - (tm - 12582912.0f);
    float p  = 1.0f + f*(0.6931472f + f*(0.2402265f + f*(0.0555041f
             + f*0.0096181f)));
    return __int_as_float(__float_as_int(p) + (__float_as_int(tm) << 23));
}

// tf32 cvt -> raw bits (dst must be .b32 reg)
__device__ __forceinline__ uint32_t tf32b(float x) {
    uint32_t r; asm("cvt.rna.tf32.f32 %0, %1;" : "=r"(r) : "f"(x));
    return r;
}
__device__ __forceinline__ float to_tf32(float x) {
    return __uint_as_float(tf32b(x));
}
__device__ __forceinline__ float4 f4_tf32(float4 v) {
    v.x = to_tf32(v.x); v.y = to_tf32(v.y);
    v.z = to_tf32(v.z); v.w = to_tf32(v.w);
    return v;
}
// m16n8k8 tf32 mma, float-reg operand form (bits in floats)
__device__ __forceinline__ void mma_tf32(float* acc, float a0, float a1,
                                         float a2, float a3, float b0, float b1) {
    uint32_t A0 = __float_as_uint(a0), A1 = __float_as_uint(a1);
    uint32_t A2 = __float_as_uint(a2), A3 = __float_as_uint(a3);
    uint32_t B0 = __float_as_uint(b0), B1 = __float_as_uint(b1);
    asm volatile(
        "mma.sync.aligned.m16n8k8.row.col.f32.tf32.tf32.f32 "
        "{%0,%1,%2,%3},{%4,%5,%6,%7},{%8,%9},{%0,%1,%2,%3};"
        : "+f"(acc[0]), "+f"(acc[1]), "+f"(acc[2]), "+f"(acc[3])
        : "r"(A0), "r"(A1), "r"(A2), "r"(A3), "r"(B0), "r"(B1));
}
// uint-operand form
__device__ __forceinline__ void mma_tf32u(float& c0, float& c1, float& c2, float& c3,
                                          uint32_t A0, uint32_t A1, uint32_t A2, uint32_t A3,
                                          uint32_t B0, uint32_t B1) {
    asm volatile(
        "mma.sync.aligned.m16n8k8.row.col.f32.tf32.tf32.f32 "
        "{%0,%1,%2,%3},{%4,%5,%6,%7},{%8,%9},{%0,%1,%2,%3};"
        : "+f"(c0), "+f"(c1), "+f"(c2), "+f"(c3)
        : "r"(A0), "r"(A1), "r"(A2), "r"(A3), "r"(B0), "r"(B1));
}

// =====================================================================
// K1: ring expvals
// =====================================================================
__global__ void qkv_kernel(const float* __restrict__ x,
                           const float* __restrict__ theta) {
    int i = blockIdx.x * 256 + threadIdx.x;       // over B*S*H = 131072
    int h  = i & (HH-1);
    int bs = i >> 6;
    const float* xp = x + bs*EE + h*DKK;
    float4 xa = *(const float4*)xp;
    float4 xb = *(const float4*)(xp + 4);
    float c0 = cosf(xa.x + theta[0]);
    float c1 = cosf(xa.y + theta[1]);
    float c2 = cosf(xa.z + theta[2]);
    float c3 = cosf(xa.w + theta[3]);
    float c4 = cosf(xb.x + theta[4]);
    float c5 = cosf(xb.y + theta[5]);
    float c6 = cosf(xb.z + theta[6]);
    float c7 = cosf(xb.w + theta[7]);
    float o1 = c0*c1;
    float o2 = o1*c2;
    float o3 = o2*c3;
    float o4 = o3*c4;
    float o5 = o4*c5;
    float o6 = o5*c6;
    float o7 = o6*c7;
    float o0 = c1*c2*c3*c4*c5*c6*c7;
    int b = bs >> 10, s = bs & (SS-1);
    float* qp = g_q + (((b*HH + h)*SS) + s)*DKK;
    *(float4*)qp       = make_float4(o0, o1, o2, o3);
    *(float4*)(qp + 4) = make_float4(o4, o5, o6, o7);
}

// =====================================================================
// K2: tensor-core attention. One CTA = (bh, 128-row tile). 8 warps,
// each warp owns 16 rows. Scores and AV both on m16n8k8 tf32 mma.
// K (=Q=V) in smem at row stride 12 floats (conflict-free B-frag loads).
// Acc->A-frag conversion for P via intra-quad shuffles (no smem, no syncs).
// =====================================================================
__global__ void __launch_bounds__(256) attn_mma_kernel() {
    __shared__ float Ks[SS*12];       // 48 KB
    const int bh   = blockIdx.x >> 3;
    const int tile = blockIdx.x & 7;

    const float* qsrc = g_q + bh*(SS*DKK);
    for (int j = threadIdx.x; j < SS*DKK/4; j += 256) {
        float4 v = ((const float4*)qsrc)[j];
        int t = j >> 1, hf = (j & 1) * 4;
        *(float4*)&Ks[t*12 + hf] = v;
    }
    __syncthreads();

    const int lane = threadIdx.x & 31, warp = threadIdx.x >> 5;
    const int g = lane >> 2, tc = lane & 3;
    const int row0 = tile*128 + warp*16;

    // Q fragments, pre-scaled by 1/sqrt(8)*log2(e), tf32-rounded once
    const float SCL = 0.35355339059f * 1.44269504089f;
    const uint32_t qa0 = tf32b(Ks[(row0+g  )*12 + tc  ] * SCL);
    const uint32_t qa1 = tf32b(Ks[(row0+g+8)*12 + tc  ] * SCL);
    const uint32_t qa2 = tf32b(Ks[(row0+g  )*12 + tc+4] * SCL);
    const uint32_t qa3 = tf32b(Ks[(row0+g+8)*12 + tc+4] * SCL);

    float o0=0.f, o1=0.f, o2=0.f, o3=0.f;   // AV accumulator (rows g,g+8 x cols 2tc,2tc+1 of d)
    float rs0=0.f, rs1=0.f;                 // rowsum partials
    const int srcA = (lane & ~3) | (tc >> 1);   // quad lane holding P col tc&~1
    const int srcB = srcA + 2;                  // quad lane holding P col (tc+4)&~1
    const bool odd = (tc & 1);

    #pragma unroll 2
    for (int t0 = 0; t0 < SS; t0 += 8) {
        // scores B-frag: B[k][n] = K[t0+n][k]  (conflict-free: banks 12g+tc)
        uint32_t sb0 = tf32b(Ks[(t0+g)*12 + tc  ]);
        uint32_t sb1 = tf32b(Ks[(t0+g)*12 + tc+4]);
        float s0=0.f, s1=0.f, s2=0.f, s3=0.f;
        mma_tf32u(s0,s1,s2,s3, qa0,qa1,qa2,qa3, sb0,sb1);

        // exp (already in log2 domain via pre-scaled Q)
        float p0 = exp2p(s0), p1 = exp2p(s1);
        float p2 = exp2p(s2), p3 = exp2p(s3);
        rs0 += p0 + p1;
        rs1 += p2 + p3;

        // accumulator layout (rows g/g+8, cols 2tc,2tc+1) -> A-frag (cols tc, tc+4)
        float a0e = __shfl_sync(0xffffffffu, p0, srcA);
        float a0o = __shfl_sync(0xffffffffu, p1, srcA);
        float a1e = __shfl_sync(0xffffffffu, p2, srcA);
        float a1o = __shfl_sync(0xffffffffu, p3, srcA);
        float a2e = __shfl_sync(0xffffffffu, p0, srcB);
        float a2o = __shfl_sync(0xffffffffu, p1, srcB);
        float a3e = __shfl_sync(0xffffffffu, p2, srcB);
        float a3o = __shfl_sync(0xffffffffu, p3, srcB);
        uint32_t pa0 = tf32b(odd ? a0o : a0e);
        uint32_t pa1 = tf32b(odd ? a1o : a1e);
        uint32_t pa2 = tf32b(odd ? a2o : a2e);
        uint32_t pa3 = tf32b(odd ? a3o : a3e);

        // AV B-frag: B[k][d] = V[t0+k][d]
        uint32_t vb0 = tf32b(Ks[(t0+tc  )*12 + g]);
        uint32_t vb1 = tf32b(Ks[(t0+tc+4)*12 + g]);
        mma_tf32u(o0,o1,o2,o3, pa0,pa1,pa2,pa3, vb0,vb1);
    }

    // rowsum quad-reduce (over tc lanes)
    rs0 += __shfl_xor_sync(0xffffffffu, rs0, 1);
    rs0 += __shfl_xor_sync(0xffffffffu, rs0, 2);
    rs1 += __shfl_xor_sync(0xffffffffu, rs1, 1);
    rs1 += __shfl_xor_sync(0xffffffffu, rs1, 2);
    float i0 = 1.0f / rs0, i1 = 1.0f / rs1;

    const int b = bh >> 6, h = bh & (HH-1);
    const int r0 = row0 + g, r1 = r0 + 8;
    float* d0 = g_attn + (b*SS + r0)*EE + h*DKK + 2*tc;
    float* d1 = g_attn + (b*SS + r1)*EE + h*DKK + 2*tc;
    *(float2*)d0 = make_float2(o0*i0, o1*i0);
    *(float2*)d1 = make_float2(o2*i1, o3*i1);
}

// =====================================================================
// tf32 tensor-core GEMM (validated R3): out = A @ W (+bias,+res,relu)
// block tile 32x128, 8 warps (2M x 4N), warp tile 16x32
// =====================================================================
template<int KTOT, bool RELU>
__global__ void __launch_bounds__(256) mma_gemm_kernel(
    const float* __restrict__ A, const float* __restrict__ W,
    const float* __restrict__ bias, const float* __restrict__ res,
    float* __restrict__ out, int N)
{
    __shared__ float As[32][36];
    __shared__ float Bs[32][136];

    const int rowbase = blockIdx.y * 32;
    const int colbase = blockIdx.x * 128;
    const int tid  = threadIdx.x;
    const int warp = tid >> 5, lane = tid & 31;
    const int wm = warp >> 2;
    const int wn = warp & 3;
    const int g  = lane >> 2, tc = lane & 3;

    float acc[4][4];
    #pragma unroll
    for (int i = 0; i < 4; i++)
        #pragma unroll
        for (int j = 0; j < 4; j++) acc[i][j] = 0.f;

    const int arow = tid >> 3, ak = (tid & 7) * 4;
    const float* Aptr = A + (rowbase + arow) * KTOT + ak;

    float4 aReg = *(const float4*)(Aptr);
    float4 bReg[4];
    #pragma unroll
    for (int i = 0; i < 4; i++) {
        int lin = tid + i*256;
        int br = lin >> 5, bc = (lin & 31) * 4;
        bReg[i] = *(const float4*)(W + br * N + colbase + bc);
    }

    const int NCHUNK = KTOT / 32;
    #pragma unroll 1
    for (int ch = 0; ch < NCHUNK; ch++) {
        __syncthreads();
        *(float4*)&As[arow][ak] = f4_tf32(aReg);
        #pragma unroll
        for (int i = 0; i < 4; i++) {
            int lin = tid + i*256;
            int br = lin >> 5, bc = (lin & 31) * 4;
            *(float4*)&Bs[br][bc] = f4_tf32(bReg[i]);
        }
        __syncthreads();

        if (ch + 1 < NCHUNK) {
            aReg = *(const float4*)(Aptr + (ch+1)*32);
            #pragma unroll
            for (int i = 0; i < 4; i++) {
                int lin = tid + i*256;
                int br = lin >> 5, bc = (lin & 31) * 4;
                bReg[i] = *(const float4*)(W + ((ch+1)*32 + br) * N + colbase + bc);
            }
        }

        #pragma unroll
        for (int ks = 0; ks < 4; ks++) {
            const int k0 = ks * 8;
            float a0 = As[wm*16 + g    ][k0 + tc];
            float a1 = As[wm*16 + g + 8][k0 + tc];
            float a2 = As[wm*16 + g    ][k0 + tc + 4];
            float a3 = As[wm*16 + g + 8][k0 + tc + 4];
            #pragma unroll
            for (int nt = 0; nt < 4; nt++) {
                int nb = wn*32 + nt*8 + g;
                float b0 = Bs[k0 + tc    ][nb];
                float b1 = Bs[k0 + tc + 4][nb];
                mma_tf32(acc[nt], a0, a1, a2, a3, b0, b1);
            }
        }
    }

    #pragma unroll
    for (int nt = 0; nt < 4; nt++) {
        int col = colbase + wn*32 + nt*8 + 2*tc;
        int r0 = rowbase + wm*16 + g;
        int r1 = r0 + 8;
        float bx = bias[col], by = bias[col+1];
        float2 v0 = make_float2(acc[nt][0] + bx, acc[nt][1] + by);
        float2 v1 = make_float2(acc[nt][2] + bx, acc[nt][3] + by);
        if (res != nullptr) {
            float2 s0 = *(const float2*)(res + r0*N + col);
            float2 s1 = *(const float2*)(res + r1*N + col);
            v0.x += s0.x; v0.y += s0.y;
            v1.x += s1.x; v1.y += s1.y;
        }
        if (RELU) {
            v0.x = fmaxf(v0.x, 0.f); v0.y = fmaxf(v0.y, 0.f);
            v1.x = fmaxf(v1.x, 0.f); v1.y = fmaxf(v1.y, 0.f);
        }
        *(float2*)(out + r0*N + col) = v0;
        *(float2*)(out + r1*N + col) = v1;
    }
}

// =====================================================================
// LN kernels
// =====================================================================
__global__ void __launch_bounds__(128) ln1_cos_kernel(
    const float* __restrict__ pre, const float* __restrict__ w,
    const float* __restrict__ b,   const float* __restrict__ thf)
{
    __shared__ float sS[4], sQ[4];
    const int row = blockIdx.x;
    const int t = threadIdx.x;
    float4 v = ((const float4*)(pre + row*EE))[t];
    float s = v.x + v.y + v.z + v.w;
    float q = v.x*v.x + v.y*v.y + v.z*v.z + v.w*v.w;
    #pragma unroll
    for (int o = 16; o; o >>= 1) {
        s += __shfl_xor_sync(0xffffffffu, s, o);
        q += __shfl_xor_sync(0xffffffffu, q, o);
    }
    if ((t & 31) == 0) { sS[t>>5] = s; sQ[t>>5] = q; }
    __syncthreads();
    s = sS[0] + sS[1] + sS[2] + sS[3];
    q = sQ[0] + sQ[1] + sQ[2] + sQ[3];
    float mu   = s * (1.0f/EE);
    float var  = q * (1.0f/EE) - mu*mu;
    float rstd = rsqrtf(var + 1e-5f);
    float4 lw = ((const float4*)w)[t];
    float4 lb = ((const float4*)b)[t];
    float4 th = ((const float4*)thf)[t];
    float4 x1;
    x1.x = (v.x - mu)*rstd*lw.x + lb.x;
    x1.y = (v.y - mu)*rstd*lw.y + lb.y;
    x1.z = (v.z - mu)*rstd*lw.z + lb.z;
    x1.w = (v.w - mu)*rstd*lw.w + lb.w;
    ((float4*)(g_x1 + row*EE))[t] = x1;
    float4 qf;
    qf.x = cosf(x1.x)*cosf(th.x);
    qf.y = cosf(x1.y)*cosf(th.y);
    qf.z = cosf(x1.z)*cosf(th.z);
    qf.w = cosf(x1.w)*cosf(th.w);
    ((float4*)(g_qf + row*EE))[t] = qf;
}

__global__ void __launch_bounds__(128) ln2_kernel(
    const float* __restrict__ pre, const float* __restrict__ w,
    const float* __restrict__ b,   float* __restrict__ out)
{
    __shared__ float sS[4], sQ[4];
    const int row = blockIdx.x;
    const int t = threadIdx.x;
    float4 v = ((const float4*)(pre + row*EE))[t];
    float s = v.x + v.y + v.z + v.w;
    float q = v.x*v.x + v.y*v.y + v.z*v.z + v.w*v.w;
    #pragma unroll
    for (int o = 16; o; o >>= 1) {
        s += __shfl_xor_sync(0xffffffffu, s, o);
        q += __shfl_xor_sync(0xffffffffu, q, o);
    }
    if ((t & 31) == 0) { sS[t>>5] = s; sQ[t>>5] = q; }
    __syncthreads();
    s = sS[0] + sS[1] + sS[2] + sS[3];
    q = sQ[0] + sQ[1] + sQ[2] + sQ[3];
    float mu   = s * (1.0f/EE);
    float var  = q * (1.0f/EE) - mu*mu;
    float rstd = rsqrtf(var + 1e-5f);
    float4 lw = ((const float4*)w)[t];
    float4 lb = ((const float4*)b)[t];
    float4 o4;
    o4.x = (v.x - mu)*rstd*lw.x + lb.x;
    o4.y = (v.y - mu)*rstd*lw.y + lb.y;
    o4.z = (v.z - mu)*rstd*lw.z + lb.z;
    o4.w = (v.w - mu)*rstd*lw.w + lb.w;
    ((float4*)(out + row*EE))[t] = o4;
}

// =====================================================================
extern "C" void kernel_launch(void* const* d_in, const int* in_sizes, int n_in,
                              void* d_out, int out_size) {
    const float* x         = (const float*)d_in[0];
    const float* theta_at  = (const float*)d_in[1];
    const float* w_combine = (const float*)d_in[2];
    const float* b_combine = (const float*)d_in[3];
    const float* theta_ffn = (const float*)d_in[4];
    const float* w1        = (const float*)d_in[5];
    const float* b1        = (const float*)d_in[6];
    const float* w2        = (const float*)d_in[7];
    const float* b2        = (const float*)d_in[8];
    const float* ln1w      = (const float*)d_in[9];
    const float* ln1b      = (const float*)d_in[10];
    const float* ln2w      = (const float*)d_in[11];
    const float* ln2b      = (const float*)d_in[12];
    float* out = (float*)d_out;

    float* d_attn; cudaGetSymbolAddress((void**)&d_attn, g_attn);
    float* d_x1;   cudaGetSymbolAddress((void**)&d_x1,   g_x1);
    float* d_qf;   cudaGetSymbolAddress((void**)&d_qf,   g_qf);
    float* d_hdn;  cudaGetSymbolAddress((void**)&d_hdn,  g_hdn);
    float* d_pre;  cudaGetSymbolAddress((void**)&d_pre,  g_pre);

    qkv_kernel<<<512, 256>>>(x, theta_at);
    attn_mma_kernel<<<1024, 256>>>();    // 128 bh x 8 row-tiles

    // combine: g_attn[2048,512] @ wc[512,512] + bias + x  -> g_pre
    mma_gemm_kernel<512, false><<<dim3(4, 64), 256>>>(
        d_attn, w_combine, b_combine, x, d_pre, EE);
    ln1_cos_kernel<<<BS, 128>>>(d_pre, ln1w, ln1b, theta_ffn);

    // ffn1: g_qf[2048,512] @ w1[512,2048] + b1, relu -> g_hdn
    mma_gemm_kernel<512, true><<<dim3(16, 64), 256>>>(
        d_qf, w1, b1, nullptr, d_hdn, FF);

    // ffn2: g_hdn[2048,2048] @ w2[2048,512] + b2 + g_x1 -> g_pre
    mma_gemm_kernel<2048, false><<<dim3(4, 64), 256>>>(
        d_hdn, w2, b2, d_x1, d_pre, EE);
    ln2_kernel<<<BS, 128>>>(d_pre, ln2w, ln2b, out);
}

// round 5
// speedup vs baseline: 2.7017x; 1.2764x over previous
#include <cuda_runtime.h>
#include <math.h>
#include <stdint.h>

#define BB 2
#define SS 1024
#define EE 512
#define HH 64
#define DKK 8
#define FF 2048
#define BS (BB*SS)   // 2048

// ---- scratch (device globals: allocation-free) ----
__device__ float g_q[BB*HH*SS*DKK];   // [B][H][S][8]
__device__ float g_attn[BS*EE];
__device__ float g_x1[BS*EE];
__device__ float g_qf[BS*EE];
__device__ float g_hdn[BS*FF];
__device__ float g_pre[BS*EE];

__device__ __forceinline__ float ex2a(float x) {
    float r; asm("ex2.approx.f32 %0, %1;" : "=f"(r) : "f"(x)); return r;
}

// m16n8k8 tf32 mma (HW truncates f32 regs to tf32; no explicit cvt)
__device__ __forceinline__ void mma_tf32(float* acc, float a0, float a1,
                                         float a2, float a3, float b0, float b1) {
    uint32_t A0 = __float_as_uint(a0), A1 = __float_as_uint(a1);
    uint32_t A2 = __float_as_uint(a2), A3 = __float_as_uint(a3);
    uint32_t B0 = __float_as_uint(b0), B1 = __float_as_uint(b1);
    asm volatile(
        "mma.sync.aligned.m16n8k8.row.col.f32.tf32.tf32.f32 "
        "{%0,%1,%2,%3},{%4,%5,%6,%7},{%8,%9},{%0,%1,%2,%3};"
        : "+f"(acc[0]), "+f"(acc[1]), "+f"(acc[2]), "+f"(acc[3])
        : "r"(A0), "r"(A1), "r"(A2), "r"(A3), "r"(B0), "r"(B1));
}
__device__ __forceinline__ void mma_tf32u(float& c0, float& c1, float& c2, float& c3,
                                          uint32_t A0, uint32_t A1, uint32_t A2, uint32_t A3,
                                          uint32_t B0, uint32_t B1) {
    asm volatile(
        "mma.sync.aligned.m16n8k8.row.col.f32.tf32.tf32.f32 "
        "{%0,%1,%2,%3},{%4,%5,%6,%7},{%8,%9},{%0,%1,%2,%3};"
        : "+f"(c0), "+f"(c1), "+f"(c2), "+f"(c3)
        : "r"(A0), "r"(A1), "r"(A2), "r"(A3), "r"(B0), "r"(B1));
}

// =====================================================================
// K1: ring expvals (__cosf: MUFU path, abs err ~1e-6)
// =====================================================================
__global__ void qkv_kernel(const float* __restrict__ x,
                           const float* __restrict__ theta) {
    int i = blockIdx.x * 256 + threadIdx.x;
    int h  = i & (HH-1);
    int bs = i >> 6;
    const float* xp = x + bs*EE + h*DKK;
    float4 xa = *(const float4*)xp;
    float4 xb = *(const float4*)(xp + 4);
    float c0 = __cosf(xa.x + theta[0]);
    float c1 = __cosf(xa.y + theta[1]);
    float c2 = __cosf(xa.z + theta[2]);
    float c3 = __cosf(xa.w + theta[3]);
    float c4 = __cosf(xb.x + theta[4]);
    float c5 = __cosf(xb.y + theta[5]);
    float c6 = __cosf(xb.z + theta[6]);
    float c7 = __cosf(xb.w + theta[7]);
    float o1 = c0*c1;
    float o2 = o1*c2;
    float o3 = o2*c3;
    float o4 = o3*c4;
    float o5 = o4*c5;
    float o6 = o5*c6;
    float o7 = o6*c7;
    float o0 = c1*c2*c3*c4*c5*c6*c7;
    int b = bs >> 10, s = bs & (SS-1);
    float* qp = g_q + (((b*HH + h)*SS) + s)*DKK;
    *(float4*)qp       = make_float4(o0, o1, o2, o3);
    *(float4*)(qp + 4) = make_float4(o4, o5, o6, o7);
}

// =====================================================================
// K2: tensor-core attention, zero-shuffle.
// Token-permuted scores B operand (row sigma(g) = (g>>1)+(g&1)*4) makes the
// scores accumulator land exactly in AV A-fragment layout:
//   C col n <-> token sigma(n); sigma(2tc)=tc, sigma(2tc+1)=tc+4
//   => lane(g,tc): p0=P[g][tc], p1=P[g][tc+4], p2=P[g+8][tc], p3=P[g+8][tc+4]
// exp via MUFU (ex2.approx). No cvt (HW tf32 truncation).
// =====================================================================
__global__ void __launch_bounds__(256) attn_mma_kernel() {
    __shared__ float Ks[SS*12];       // 48 KB, row stride 12
    const int bh   = blockIdx.x >> 3;
    const int tile = blockIdx.x & 7;

    const float* qsrc = g_q + bh*(SS*DKK);
    for (int j = threadIdx.x; j < SS*DKK/4; j += 256) {
        float4 v = ((const float4*)qsrc)[j];
        int t = j >> 1, hf = (j & 1) * 4;
        *(float4*)&Ks[t*12 + hf] = v;
    }
    __syncthreads();

    const int lane = threadIdx.x & 31, warp = threadIdx.x >> 5;
    const int g = lane >> 2, tc = lane & 3;
    const int sg = (g >> 1) + (g & 1)*4;     // sigma(g)
    const int row0 = tile*128 + warp*16;

    // Q fragments pre-scaled by 1/sqrt(8)*log2(e)
    const float SCL = 0.35355339059f * 1.44269504089f;
    const uint32_t qa0 = __float_as_uint(Ks[(row0+g  )*12 + tc  ] * SCL);
    const uint32_t qa1 = __float_as_uint(Ks[(row0+g+8)*12 + tc  ] * SCL);
    const uint32_t qa2 = __float_as_uint(Ks[(row0+g  )*12 + tc+4] * SCL);
    const uint32_t qa3 = __float_as_uint(Ks[(row0+g+8)*12 + tc+4] * SCL);

    float o0=0.f, o1=0.f, o2=0.f, o3=0.f;
    float rs0=0.f, rs1=0.f;

    #pragma unroll 4
    for (int t0 = 0; t0 < SS; t0 += 8) {
        // scores B-frag, token-permuted rows (conflict-free: 12*sigma(g)+tc)
        uint32_t sb0 = __float_as_uint(Ks[(t0+sg)*12 + tc  ]);
        uint32_t sb1 = __float_as_uint(Ks[(t0+sg)*12 + tc+4]);
        float s0=0.f, s1=0.f, s2=0.f, s3=0.f;
        mma_tf32u(s0,s1,s2,s3, qa0,qa1,qa2,qa3, sb0,sb1);

        // exp2 on MUFU (log2 domain via pre-scaled Q)
        float p0 = ex2a(s0), p1 = ex2a(s1);
        float p2 = ex2a(s2), p3 = ex2a(s3);
        rs0 += p0 + p1;                     // row g: tokens tc, tc+4
        rs1 += p2 + p3;                     // row g+8

        // AV: A-frag = (p0, p2, p1, p3) directly (a0,a1,a2,a3 order)
        uint32_t vb0 = __float_as_uint(Ks[(t0+tc  )*12 + g]);
        uint32_t vb1 = __float_as_uint(Ks[(t0+tc+4)*12 + g]);
        mma_tf32u(o0,o1,o2,o3,
                  __float_as_uint(p0), __float_as_uint(p2),
                  __float_as_uint(p1), __float_as_uint(p3),
                  vb0, vb1);
    }

    rs0 += __shfl_xor_sync(0xffffffffu, rs0, 1);
    rs0 += __shfl_xor_sync(0xffffffffu, rs0, 2);
    rs1 += __shfl_xor_sync(0xffffffffu, rs1, 1);
    rs1 += __shfl_xor_sync(0xffffffffu, rs1, 2);
    float i0 = 1.0f / rs0, i1 = 1.0f / rs1;

    const int b = bh >> 6, h = bh & (HH-1);
    const int r0 = row0 + g, r1 = r0 + 8;
    float* d0 = g_attn + (b*SS + r0)*EE + h*DKK + 2*tc;
    float* d1 = g_attn + (b*SS + r1)*EE + h*DKK + 2*tc;
    *(float2*)d0 = make_float2(o0*i0, o1*i0);
    *(float2*)d1 = make_float2(o2*i1, o3*i1);
}

// =====================================================================
// tf32 tensor-core GEMM: out = A @ W (+bias,+res,relu)
// block tile 32x128, 8 warps (2M x 4N), warp tile 16x32
// =====================================================================
template<int KTOT, bool RELU>
__global__ void __launch_bounds__(256) mma_gemm_kernel(
    const float* __restrict__ A, const float* __restrict__ W,
    const float* __restrict__ bias, const float* __restrict__ res,
    float* __restrict__ out, int N)
{
    __shared__ float As[32][36];
    __shared__ float Bs[32][136];

    const int rowbase = blockIdx.y * 32;
    const int colbase = blockIdx.x * 128;
    const int tid  = threadIdx.x;
    const int warp = tid >> 5, lane = tid & 31;
    const int wm = warp >> 2;
    const int wn = warp & 3;
    const int g  = lane >> 2, tc = lane & 3;

    float acc[4][4];
    #pragma unroll
    for (int i = 0; i < 4; i++)
        #pragma unroll
        for (int j = 0; j < 4; j++) acc[i][j] = 0.f;

    const int arow = tid >> 3, ak = (tid & 7) * 4;
    const float* Aptr = A + (rowbase + arow) * KTOT + ak;

    float4 aReg = *(const float4*)(Aptr);
    float4 bReg[4];
    #pragma unroll
    for (int i = 0; i < 4; i++) {
        int lin = tid + i*256;
        int br = lin >> 5, bc = (lin & 31) * 4;
        bReg[i] = *(const float4*)(W + br * N + colbase + bc);
    }

    const int NCHUNK = KTOT / 32;
    #pragma unroll 1
    for (int ch = 0; ch < NCHUNK; ch++) {
        __syncthreads();
        *(float4*)&As[arow][ak] = aReg;
        #pragma unroll
        for (int i = 0; i < 4; i++) {
            int lin = tid + i*256;
            int br = lin >> 5, bc = (lin & 31) * 4;
            *(float4*)&Bs[br][bc] = bReg[i];
        }
        __syncthreads();

        if (ch + 1 < NCHUNK) {
            aReg = *(const float4*)(Aptr + (ch+1)*32);
            #pragma unroll
            for (int i = 0; i < 4; i++) {
                int lin = tid + i*256;
                int br = lin >> 5, bc = (lin & 31) * 4;
                bReg[i] = *(const float4*)(W + ((ch+1)*32 + br) * N + colbase + bc);
            }
        }

        #pragma unroll
        for (int ks = 0; ks < 4; ks++) {
            const int k0 = ks * 8;
            float a0 = As[wm*16 + g    ][k0 + tc];
            float a1 = As[wm*16 + g + 8][k0 + tc];
            float a2 = As[wm*16 + g    ][k0 + tc + 4];
            float a3 = As[wm*16 + g + 8][k0 + tc + 4];
            #pragma unroll
            for (int nt = 0; nt < 4; nt++) {
                int nb = wn*32 + nt*8 + g;
                float b0 = Bs[k0 + tc    ][nb];
                float b1 = Bs[k0 + tc + 4][nb];
                mma_tf32(acc[nt], a0, a1, a2, a3, b0, b1);
            }
        }
    }

    #pragma unroll
    for (int nt = 0; nt < 4; nt++) {
        int col = colbase + wn*32 + nt*8 + 2*tc;
        int r0 = rowbase + wm*16 + g;
        int r1 = r0 + 8;
        float bx = bias[col], by = bias[col+1];
        float2 v0 = make_float2(acc[nt][0] + bx, acc[nt][1] + by);
        float2 v1 = make_float2(acc[nt][2] + bx, acc[nt][3] + by);
        if (res != nullptr) {
            float2 s0 = *(const float2*)(res + r0*N + col);
            float2 s1 = *(const float2*)(res + r1*N + col);
            v0.x += s0.x; v0.y += s0.y;
            v1.x += s1.x; v1.y += s1.y;
        }
        if (RELU) {
            v0.x = fmaxf(v0.x, 0.f); v0.y = fmaxf(v0.y, 0.f);
            v1.x = fmaxf(v1.x, 0.f); v1.y = fmaxf(v1.y, 0.f);
        }
        *(float2*)(out + r0*N + col) = v0;
        *(float2*)(out + r1*N + col) = v1;
    }
}

// =====================================================================
// LN kernels
// =====================================================================
__global__ void __launch_bounds__(128) ln1_cos_kernel(
    const float* __restrict__ pre, const float* __restrict__ w,
    const float* __restrict__ b,   const float* __restrict__ thf)
{
    __shared__ float sS[4], sQ[4];
    const int row = blockIdx.x;
    const int t = threadIdx.x;
    float4 v = ((const float4*)(pre + row*EE))[t];
    float s = v.x + v.y + v.z + v.w;
    float q = v.x*v.x + v.y*v.y + v.z*v.z + v.w*v.w;
    #pragma unroll
    for (int o = 16; o; o >>= 1) {
        s += __shfl_xor_sync(0xffffffffu, s, o);
        q += __shfl_xor_sync(0xffffffffu, q, o);
    }
    if ((t & 31) == 0) { sS[t>>5] = s; sQ[t>>5] = q; }
    __syncthreads();
    s = sS[0] + sS[1] + sS[2] + sS[3];
    q = sQ[0] + sQ[1] + sQ[2] + sQ[3];
    float mu   = s * (1.0f/EE);
    float var  = q * (1.0f/EE) - mu*mu;
    float rstd = rsqrtf(var + 1e-5f);
    float4 lw = ((const float4*)w)[t];
    float4 lb = ((const float4*)b)[t];
    float4 th = ((const float4*)thf)[t];
    float4 x1;
    x1.x = (v.x - mu)*rstd*lw.x + lb.x;
    x1.y = (v.y - mu)*rstd*lw.y + lb.y;
    x1.z = (v.z - mu)*rstd*lw.z + lb.z;
    x1.w = (v.w - mu)*rstd*lw.w + lb.w;
    ((float4*)(g_x1 + row*EE))[t] = x1;
    float4 qf;
    qf.x = __cosf(x1.x)*__cosf(th.x);
    qf.y = __cosf(x1.y)*__cosf(th.y);
    qf.z = __cosf(x1.z)*__cosf(th.z);
    qf.w = __cosf(x1.w)*__cosf(th.w);
    ((float4*)(g_qf + row*EE))[t] = qf;
}

__global__ void __launch_bounds__(128) ln2_kernel(
    const float* __restrict__ pre, const float* __restrict__ w,
    const float* __restrict__ b,   float* __restrict__ out)
{
    __shared__ float sS[4], sQ[4];
    const int row = blockIdx.x;
    const int t = threadIdx.x;
    float4 v = ((const float4*)(pre + row*EE))[t];
    float s = v.x + v.y + v.z + v.w;
    float q = v.x*v.x + v.y*v.y + v.z*v.z + v.w*v.w;
    #pragma unroll
    for (int o = 16; o; o >>= 1) {
        s += __shfl_xor_sync(0xffffffffu, s, o);
        q += __shfl_xor_sync(0xffffffffu, q, o);
    }
    if ((t & 31) == 0) { sS[t>>5] = s; sQ[t>>5] = q; }
    __syncthreads();
    s = sS[0] + sS[1] + sS[2] + sS[3];
    q = sQ[0] + sQ[1] + sQ[2] + sQ[3];
    float mu   = s * (1.0f/EE);
    float var  = q * (1.0f/EE) - mu*mu;
    float rstd = rsqrtf(var + 1e-5f);
    float4 lw = ((const float4*)w)[t];
    float4 lb = ((const float4*)b)[t];
    float4 o4;
    o4.x = (v.x - mu)*rstd*lw.x + lb.x;
    o4.y = (v.y - mu)*rstd*lw.y + lb.y;
    o4.z = (v.z - mu)*rstd*lw.z + lb.z;
    o4.w = (v.w - mu)*rstd*lw.w + lb.w;
    ((float4*)(out + row*EE))[t] = o4;
}

// =====================================================================
extern "C" void kernel_launch(void* const* d_in, const int* in_sizes, int n_in,
                              void* d_out, int out_size) {
    const float* x         = (const float*)d_in[0];
    const float* theta_at  = (const float*)d_in[1];
    const float* w_combine = (const float*)d_in[2];
    const float* b_combine = (const float*)d_in[3];
    const float* theta_ffn = (const float*)d_in[4];
    const float* w1        = (const float*)d_in[5];
    const float* b1        = (const float*)d_in[6];
    const float* w2        = (const float*)d_in[7];
    const float* b2        = (const float*)d_in[8];
    const float* ln1w      = (const float*)d_in[9];
    const float* ln1b      = (const float*)d_in[10];
    const float* ln2w      = (const float*)d_in[11];
    const float* ln2b      = (const float*)d_in[12];
    float* out = (float*)d_out;

    float* d_attn; cudaGetSymbolAddress((void**)&d_attn, g_attn);
    float* d_x1;   cudaGetSymbolAddress((void**)&d_x1,   g_x1);
    float* d_qf;   cudaGetSymbolAddress((void**)&d_qf,   g_qf);
    float* d_hdn;  cudaGetSymbolAddress((void**)&d_hdn,  g_hdn);
    float* d_pre;  cudaGetSymbolAddress((void**)&d_pre,  g_pre);

    qkv_kernel<<<512, 256>>>(x, theta_at);
    attn_mma_kernel<<<1024, 256>>>();

    mma_gemm_kernel<512, false><<<dim3(4, 64), 256>>>(
        d_attn, w_combine, b_combine, x, d_pre, EE);
    ln1_cos_kernel<<<BS, 128>>>(d_pre, ln1w, ln1b, theta_ffn);

    mma_gemm_kernel<512, true><<<dim3(16, 64), 256>>>(
        d_qf, w1, b1, nullptr, d_hdn, FF);

    mma_gemm_kernel<2048, false><<<dim3(4, 64), 256>>>(
        d_hdn, w2, b2, d_x1, d_pre, EE);
    ln2_kernel<<<BS, 128>>>(d_pre, ln2w, ln2b, out);
}

// round 6
// speedup vs baseline: 2.7021x; 1.0002x over previous
#include <cuda_runtime.h>
#include <math.h>
#include <stdint.h>

#define BB 2
#define SS 1024
#define EE 512
#define HH 64
#define DKK 8
#define FF 2048
#define BS (BB*SS)   // 2048

// ---- scratch (device globals: allocation-free) ----
__device__ float g_q[BB*HH*SS*DKK];   // [B][H][S][8]
__device__ float g_attn[BS*EE];
__device__ float g_x1[BS*EE];
__device__ float g_qf[BS*EE];
__device__ float g_hdn[BS*FF];
__device__ float g_pre[BS*EE];

__device__ __forceinline__ float ex2a(float x) {
    float r; asm("ex2.approx.f32 %0, %1;" : "=f"(r) : "f"(x)); return r;
}

// m16n8k8 tf32 mma (HW truncates f32 regs to tf32)
__device__ __forceinline__ void mma_tf32(float* acc, float a0, float a1,
                                         float a2, float a3, float b0, float b1) {
    uint32_t A0 = __float_as_uint(a0), A1 = __float_as_uint(a1);
    uint32_t A2 = __float_as_uint(a2), A3 = __float_as_uint(a3);
    uint32_t B0 = __float_as_uint(b0), B1 = __float_as_uint(b1);
    asm volatile(
        "mma.sync.aligned.m16n8k8.row.col.f32.tf32.tf32.f32 "
        "{%0,%1,%2,%3},{%4,%5,%6,%7},{%8,%9},{%0,%1,%2,%3};"
        : "+f"(acc[0]), "+f"(acc[1]), "+f"(acc[2]), "+f"(acc[3])
        : "r"(A0), "r"(A1), "r"(A2), "r"(A3), "r"(B0), "r"(B1));
}
__device__ __forceinline__ void mma_tf32u(float& c0, float& c1, float& c2, float& c3,
                                          uint32_t A0, uint32_t A1, uint32_t A2, uint32_t A3,
                                          uint32_t B0, uint32_t B1) {
    asm volatile(
        "mma.sync.aligned.m16n8k8.row.col.f32.tf32.tf32.f32 "
        "{%0,%1,%2,%3},{%4,%5,%6,%7},{%8,%9},{%0,%1,%2,%3};"
        : "+f"(c0), "+f"(c1), "+f"(c2), "+f"(c3)
        : "r"(A0), "r"(A1), "r"(A2), "r"(A3), "r"(B0), "r"(B1));
}

// =====================================================================
// K1: ring expvals
// =====================================================================
__global__ void qkv_kernel(const float* __restrict__ x,
                           const float* __restrict__ theta) {
    int i = blockIdx.x * 256 + threadIdx.x;
    int h  = i & (HH-1);
    int bs = i >> 6;
    const float* xp = x + bs*EE + h*DKK;
    float4 xa = *(const float4*)xp;
    float4 xb = *(const float4*)(xp + 4);
    float c0 = __cosf(xa.x + theta[0]);
    float c1 = __cosf(xa.y + theta[1]);
    float c2 = __cosf(xa.z + theta[2]);
    float c3 = __cosf(xa.w + theta[3]);
    float c4 = __cosf(xb.x + theta[4]);
    float c5 = __cosf(xb.y + theta[5]);
    float c6 = __cosf(xb.z + theta[6]);
    float c7 = __cosf(xb.w + theta[7]);
    float o1 = c0*c1;
    float o2 = o1*c2;
    float o3 = o2*c3;
    float o4 = o3*c4;
    float o5 = o4*c5;
    float o6 = o5*c6;
    float o7 = o6*c7;
    float o0 = c1*c2*c3*c4*c5*c6*c7;
    int b = bs >> 10, s = bs & (SS-1);
    float* qp = g_q + (((b*HH + h)*SS) + s)*DKK;
    *(float4*)qp       = make_float4(o0, o1, o2, o3);
    *(float4*)(qp + 4) = make_float4(o4, o5, o6, o7);
}

// =====================================================================
// K2: tensor-core attention, zero-shuffle, dual-strip (16 tokens/iter).
// Token-permuted scores B operand (sigma(g) = (g>>1)+(g&1)*4) puts the
// scores accumulator directly in AV A-fragment layout.
// Two independent strips + two accumulator sets per iteration: breaks the
// AV loop-carried chain, overlaps MUFU exp under the MMA pipe.
// =====================================================================
__global__ void __launch_bounds__(256, 4) attn_mma_kernel() {
    __shared__ float Ks[SS*12];       // exactly 48 KB, row stride 12
    const int bh   = blockIdx.x >> 3;
    const int tile = blockIdx.x & 7;

    const float* qsrc = g_q + bh*(SS*DKK);
    for (int j = threadIdx.x; j < SS*DKK/4; j += 256) {
        float4 v = ((const float4*)qsrc)[j];
        int t = j >> 1, hf = (j & 1) * 4;
        *(float4*)&Ks[t*12 + hf] = v;
    }
    __syncthreads();

    const int lane = threadIdx.x & 31, warp = threadIdx.x >> 5;
    const int g = lane >> 2, tc = lane & 3;
    const int sg = (g >> 1) + (g & 1)*4;     // sigma(g)
    const int row0 = tile*128 + warp*16;

    const float SCL = 0.35355339059f * 1.44269504089f;   // 1/sqrt(8)*log2(e)
    const uint32_t qa0 = __float_as_uint(Ks[(row0+g  )*12 + tc  ] * SCL);
    const uint32_t qa1 = __float_as_uint(Ks[(row0+g+8)*12 + tc  ] * SCL);
    const uint32_t qa2 = __float_as_uint(Ks[(row0+g  )*12 + tc+4] * SCL);
    const uint32_t qa3 = __float_as_uint(Ks[(row0+g+8)*12 + tc+4] * SCL);

    float oa0=0.f, oa1=0.f, oa2=0.f, oa3=0.f;   // AV acc, even strips
    float ob0=0.f, ob1=0.f, ob2=0.f, ob3=0.f;   // AV acc, odd strips
    float ra0=0.f, ra1=0.f, rb0=0.f, rb1=0.f;   // rowsum partials

    #pragma unroll 2
    for (int t0 = 0; t0 < SS; t0 += 16) {
        const int tA = t0, tB = t0 + 8;
        // scores B-frags (token-permuted rows; conflict-free banks)
        uint32_t sA0 = __float_as_uint(Ks[(tA+sg)*12 + tc  ]);
        uint32_t sA1 = __float_as_uint(Ks[(tA+sg)*12 + tc+4]);
        uint32_t sB0 = __float_as_uint(Ks[(tB+sg)*12 + tc  ]);
        uint32_t sB1 = __float_as_uint(Ks[(tB+sg)*12 + tc+4]);
        float a0=0.f,a1=0.f,a2=0.f,a3=0.f;
        float b0=0.f,b1=0.f,b2=0.f,b3=0.f;
        mma_tf32u(a0,a1,a2,a3, qa0,qa1,qa2,qa3, sA0,sA1);
        mma_tf32u(b0,b1,b2,b3, qa0,qa1,qa2,qa3, sB0,sB1);

        // exp2 on MUFU (log2 domain via pre-scaled Q)
        float pA0 = ex2a(a0), pA1 = ex2a(a1), pA2 = ex2a(a2), pA3 = ex2a(a3);
        float pB0 = ex2a(b0), pB1 = ex2a(b1), pB2 = ex2a(b2), pB3 = ex2a(b3);
        ra0 += pA0 + pA1;  ra1 += pA2 + pA3;
        rb0 += pB0 + pB1;  rb1 += pB2 + pB3;

        // AV B-frags
        uint32_t vA0 = __float_as_uint(Ks[(tA+tc  )*12 + g]);
        uint32_t vA1 = __float_as_uint(Ks[(tA+tc+4)*12 + g]);
        uint32_t vB0 = __float_as_uint(Ks[(tB+tc  )*12 + g]);
        uint32_t vB1 = __float_as_uint(Ks[(tB+tc+4)*12 + g]);
        // A-frag = (p0, p2, p1, p3) directly (permuted-token layout)
        mma_tf32u(oa0,oa1,oa2,oa3,
                  __float_as_uint(pA0), __float_as_uint(pA2),
                  __float_as_uint(pA1), __float_as_uint(pA3), vA0, vA1);
        mma_tf32u(ob0,ob1,ob2,ob3,
                  __float_as_uint(pB0), __float_as_uint(pB2),
                  __float_as_uint(pB1), __float_as_uint(pB3), vB0, vB1);
    }

    float rs0 = ra0 + rb0, rs1 = ra1 + rb1;
    rs0 += __shfl_xor_sync(0xffffffffu, rs0, 1);
    rs0 += __shfl_xor_sync(0xffffffffu, rs0, 2);
    rs1 += __shfl_xor_sync(0xffffffffu, rs1, 1);
    rs1 += __shfl_xor_sync(0xffffffffu, rs1, 2);
    float i0 = 1.0f / rs0, i1 = 1.0f / rs1;

    const int b = bh >> 6, h = bh & (HH-1);
    const int r0 = row0 + g, r1 = r0 + 8;
    float* d0 = g_attn + (b*SS + r0)*EE + h*DKK + 2*tc;
    float* d1 = g_attn + (b*SS + r1)*EE + h*DKK + 2*tc;
    *(float2*)d0 = make_float2((oa0+ob0)*i0, (oa1+ob1)*i0);
    *(float2*)d1 = make_float2((oa2+ob2)*i1, (oa3+ob3)*i1);
}

// =====================================================================
// tf32 tensor-core GEMM: out = A @ W (+bias,+res,relu)
// =====================================================================
template<int KTOT, bool RELU>
__global__ void __launch_bounds__(256) mma_gemm_kernel(
    const float* __restrict__ A, const float* __restrict__ W,
    const float* __restrict__ bias, const float* __restrict__ res,
    float* __restrict__ out, int N)
{
    __shared__ float As[32][36];
    __shared__ float Bs[32][136];

    const int rowbase = blockIdx.y * 32;
    const int colbase = blockIdx.x * 128;
    const int tid  = threadIdx.x;
    const int warp = tid >> 5, lane = tid & 31;
    const int wm = warp >> 2;
    const int wn = warp & 3;
    const int g  = lane >> 2, tc = lane & 3;

    float acc[4][4];
    #pragma unroll
    for (int i = 0; i < 4; i++)
        #pragma unroll
        for (int j = 0; j < 4; j++) acc[i][j] = 0.f;

    const int arow = tid >> 3, ak = (tid & 7) * 4;
    const float* Aptr = A + (rowbase + arow) * KTOT + ak;

    float4 aReg = *(const float4*)(Aptr);
    float4 bReg[4];
    #pragma unroll
    for (int i = 0; i < 4; i++) {
        int lin = tid + i*256;
        int br = lin >> 5, bc = (lin & 31) * 4;
        bReg[i] = *(const float4*)(W + br * N + colbase + bc);
    }

    const int NCHUNK = KTOT / 32;
    #pragma unroll 1
    for (int ch = 0; ch < NCHUNK; ch++) {
        __syncthreads();
        *(float4*)&As[arow][ak] = aReg;
        #pragma unroll
        for (int i = 0; i < 4; i++) {
            int lin = tid + i*256;
            int br = lin >> 5, bc = (lin & 31) * 4;
            *(float4*)&Bs[br][bc] = bReg[i];
        }
        __syncthreads();

        if (ch + 1 < NCHUNK) {
            aReg = *(const float4*)(Aptr + (ch+1)*32);
            #pragma unroll
            for (int i = 0; i < 4; i++) {
                int lin = tid + i*256;
                int br = lin >> 5, bc = (lin & 31) * 4;
                bReg[i] = *(const float4*)(W + ((ch+1)*32 + br) * N + colbase + bc);
            }
        }

        #pragma unroll
        for (int ks = 0; ks < 4; ks++) {
            const int k0 = ks * 8;
            float a0 = As[wm*16 + g    ][k0 + tc];
            float a1 = As[wm*16 + g + 8][k0 + tc];
            float a2 = As[wm*16 + g    ][k0 + tc + 4];
            float a3 = As[wm*16 + g + 8][k0 + tc + 4];
            #pragma unroll
            for (int nt = 0; nt < 4; nt++) {
                int nb = wn*32 + nt*8 + g;
                float b0 = Bs[k0 + tc    ][nb];
                float b1 = Bs[k0 + tc + 4][nb];
                mma_tf32(acc[nt], a0, a1, a2, a3, b0, b1);
            }
        }
    }

    #pragma unroll
    for (int nt = 0; nt < 4; nt++) {
        int col = colbase + wn*32 + nt*8 + 2*tc;
        int r0 = rowbase + wm*16 + g;
        int r1 = r0 + 8;
        float bx = bias[col], by = bias[col+1];
        float2 v0 = make_float2(acc[nt][0] + bx, acc[nt][1] + by);
        float2 v1 = make_float2(acc[nt][2] + bx, acc[nt][3] + by);
        if (res != nullptr) {
            float2 s0 = *(const float2*)(res + r0*N + col);
            float2 s1 = *(const float2*)(res + r1*N + col);
            v0.x += s0.x; v0.y += s0.y;
            v1.x += s1.x; v1.y += s1.y;
        }
        if (RELU) {
            v0.x = fmaxf(v0.x, 0.f); v0.y = fmaxf(v0.y, 0.f);
            v1.x = fmaxf(v1.x, 0.f); v1.y = fmaxf(v1.y, 0.f);
        }
        *(float2*)(out + r0*N + col) = v0;
        *(float2*)(out + r1*N + col) = v1;
    }
}

// =====================================================================
// LN kernels
// =====================================================================
__global__ void __launch_bounds__(128) ln1_cos_kernel(
    const float* __restrict__ pre, const float* __restrict__ w,
    const float* __restrict__ b,   const float* __restrict__ thf)
{
    __shared__ float sS[4], sQ[4];
    const int row = blockIdx.x;
    const int t = threadIdx.x;
    float4 v = ((const float4*)(pre + row*EE))[t];
    float s = v.x + v.y + v.z + v.w;
    float q = v.x*v.x + v.y*v.y + v.z*v.z + v.w*v.w;
    #pragma unroll
    for (int o = 16; o; o >>= 1) {
        s += __shfl_xor_sync(0xffffffffu, s, o);
        q += __shfl_xor_sync(0xffffffffu, q, o);
    }
    if ((t & 31) == 0) { sS[t>>5] = s; sQ[t>>5] = q; }
    __syncthreads();
    s = sS[0] + sS[1] + sS[2] + sS[3];
    q = sQ[0] + sQ[1] + sQ[2] + sQ[3];
    float mu   = s * (1.0f/EE);
    float var  = q * (1.0f/EE) - mu*mu;
    float rstd = rsqrtf(var + 1e-5f);
    float4 lw = ((const float4*)w)[t];
    float4 lb = ((const float4*)b)[t];
    float4 th = ((const float4*)thf)[t];
    float4 x1;
    x1.x = (v.x - mu)*rstd*lw.x + lb.x;
    x1.y = (v.y - mu)*rstd*lw.y + lb.y;
    x1.z = (v.z - mu)*rstd*lw.z + lb.z;
    x1.w = (v.w - mu)*rstd*lw.w + lb.w;
    ((float4*)(g_x1 + row*EE))[t] = x1;
    float4 qf;
    qf.x = __cosf(x1.x)*__cosf(th.x);
    qf.y = __cosf(x1.y)*__cosf(th.y);
    qf.z = __cosf(x1.z)*__cosf(th.z);
    qf.w = __cosf(x1.w)*__cosf(th.w);
    ((float4*)(g_qf + row*EE))[t] = qf;
}

__global__ void __launch_bounds__(128) ln2_kernel(
    const float* __restrict__ pre, const float* __restrict__ w,
    const float* __restrict__ b,   float* __restrict__ out)
{
    __shared__ float sS[4], sQ[4];
    const int row = blockIdx.x;
    const int t = threadIdx.x;
    float4 v = ((const float4*)(pre + row*EE))[t];
    float s = v.x + v.y + v.z + v.w;
    float q = v.x*v.x + v.y*v.y + v.z*v.z + v.w*v.w;
    #pragma unroll
    for (int o = 16; o; o >>= 1) {
        s += __shfl_xor_sync(0xffffffffu, s, o);
        q += __shfl_xor_sync(0xffffffffu, q, o);
    }
    if ((t & 31) == 0) { sS[t>>5] = s; sQ[t>>5] = q; }
    __syncthreads();
    s = sS[0] + sS[1] + sS[2] + sS[3];
    q = sQ[0] + sQ[1] + sQ[2] + sQ[3];
    float mu   = s * (1.0f/EE);
    float var  = q * (1.0f/EE) - mu*mu;
    float rstd = rsqrtf(var + 1e-5f);
    float4 lw = ((const float4*)w)[t];
    float4 lb = ((const float4*)b)[t];
    float4 o4;
    o4.x = (v.x - mu)*rstd*lw.x + lb.x;
    o4.y = (v.y - mu)*rstd*lw.y + lb.y;
    o4.z = (v.z - mu)*rstd*lw.z + lb.z;
    o4.w = (v.w - mu)*rstd*lw.w + lb.w;
    ((float4*)(out + row*EE))[t] = o4;
}

// =====================================================================
extern "C" void kernel_launch(void* const* d_in, const int* in_sizes, int n_in,
                              void* d_out, int out_size) {
    const float* x         = (const float*)d_in[0];
    const float* theta_at  = (const float*)d_in[1];
    const float* w_combine = (const float*)d_in[2];
    const float* b_combine = (const float*)d_in[3];
    const float* theta_ffn = (const float*)d_in[4];
    const float* w1        = (const float*)d_in[5];
    const float* b1        = (const float*)d_in[6];
    const float* w2        = (const float*)d_in[7];
    const float* b2        = (const float*)d_in[8];
    const float* ln1w      = (const float*)d_in[9];
    const float* ln1b      = (const float*)d_in[10];
    const float* ln2w      = (const float*)d_in[11];
    const float* ln2b      = (const float*)d_in[12];
    float* out = (float*)d_out;

    float* d_attn; cudaGetSymbolAddress((void**)&d_attn, g_attn);
    float* d_x1;   cudaGetSymbolAddress((void**)&d_x1,   g_x1);
    float* d_qf;   cudaGetSymbolAddress((void**)&d_qf,   g_qf);
    float* d_hdn;  cudaGetSymbolAddress((void**)&d_hdn,  g_hdn);
    float* d_pre;  cudaGetSymbolAddress((void**)&d_pre,  g_pre);

    qkv_kernel<<<512, 256>>>(x, theta_at);
    attn_mma_kernel<<<1024, 256>>>();

    mma_gemm_kernel<512, false><<<dim3(4, 64), 256>>>(
        d_attn, w_combine, b_combine, x, d_pre, EE);
    ln1_cos_kernel<<<BS, 128>>>(d_pre, ln1w, ln1b, theta_ffn);

    mma_gemm_kernel<512, true><<<dim3(16, 64), 256>>>(
        d_qf, w1, b1, nullptr, d_hdn, FF);

    mma_gemm_kernel<2048, false><<<dim3(4, 64), 256>>>(
        d_hdn, w2, b2, d_x1, d_pre, EE);
    ln2_kernel<<<BS, 128>>>(d_pre, ln2w, ln2b, out);
}